// round 9
// baseline (speedup 1.0000x reference)
#include <cuda_runtime.h>
#include <math.h>
#include <float.h>

#define Bb   512
#define Cc   2048
#define HWn  48
#define NAT  51
#define HIDn 128
#define S1   16    // K-splits for pooledC @ W1^T
#define S3   16    // K-splits for bmean @ Wl^T
#define NTIL 32    // channel tiles in gate kernel (2048/64)

// Scratch (static __device__ globals — zero-initialized by CUDA)
__device__ float g_pooled[Bb * Cc];
__device__ float g_bmean [Bb * Cc];
__device__ float g_hp    [S1 * Bb * HIDn];
__device__ float g_h     [Bb * HIDn];
__device__ float g_zp    [NTIL * NAT * Bb];    // front sig @ Wl^T partials [nt][j][b-orig]
__device__ float g_zbp   [S3 * NAT * Bb];      // bmean @ Wl^T partials     [s][j][b]
__device__ int   g_idx   [Bb];                 // compacted front-row -> original b
__device__ int   g_nf;                         // number of front rows

// ---------------------------------------------------------------------------
// K1: streaming pass (unchanged — proven, near HBM bound).
// ---------------------------------------------------------------------------
__global__ void __launch_bounds__(256) k1_reduce(
    const float* __restrict__ body, const float* __restrict__ face,
    const float* __restrict__ Af,   const int*   __restrict__ pose)
{
    __shared__ float sm_s[8][96];
    __shared__ float sm_m[8][96];
    __shared__ float out_s[64], out_m[64];
    int tid  = threadIdx.x;
    int wid  = tid >> 5;
    int lane = tid & 31;
    int blk_ch = blockIdx.x * 64;
    int b = blk_ch >> 11;
    bool front = (pose[b] == 1);
    int wbase = blk_ch + wid * 8;

    const float4* bp4 = (const float4*)body + (size_t)wbase * 12;
    float4 bv[3];
    #pragma unroll
    for (int k = 0; k < 3; k++)
        bv[k] = bp4[k * 32 + lane];
    if (front) {
        const float4* fp4 = (const float4*)face + (size_t)wbase * 12;
        const float4* ap4 = (const float4*)Af   + (size_t)(wbase & (Cc - 1)) * 12;
        #pragma unroll
        for (int k = 0; k < 3; k++) {
            float4 fv = fp4[k * 32 + lane];
            float4 av = ap4[k * 32 + lane];
            float m01 = fmaxf(bv[k].x * av.x * fv.x, bv[k].y * av.y * fv.y);
            float m23 = fmaxf(bv[k].z * av.z * fv.z, bv[k].w * av.w * fv.w);
            sm_m[wid][k * 32 + lane] = fmaxf(m01, m23);
        }
    }
    #pragma unroll
    for (int k = 0; k < 3; k++)
        sm_s[wid][k * 32 + lane] = (bv[k].x + bv[k].y) + (bv[k].z + bv[k].w);
    __syncthreads();

    {
        int chl = tid >> 2;
        int w2  = chl >> 3;
        int off = (chl & 7) * 12 + (tid & 3) * 3;
        float ss = sm_s[w2][off] + sm_s[w2][off + 1] + sm_s[w2][off + 2];
        ss += __shfl_xor_sync(0xffffffffu, ss, 1);
        ss += __shfl_xor_sync(0xffffffffu, ss, 2);
        float mm = 0.f;
        if (front) {
            mm = fmaxf(fmaxf(sm_m[w2][off], sm_m[w2][off + 1]), sm_m[w2][off + 2]);
            mm = fmaxf(mm, __shfl_xor_sync(0xffffffffu, mm, 1));
            mm = fmaxf(mm, __shfl_xor_sync(0xffffffffu, mm, 2));
        }
        if ((tid & 3) == 0) {
            out_s[chl] = ss * (1.0f / 48.0f);
            out_m[chl] = mm;
        }
    }
    __syncthreads();
    if (tid < 64)        g_bmean [blk_ch + tid]      = out_s[tid];
    else if (tid < 128)  g_pooled[blk_ch + tid - 64] = out_m[tid - 64];
}

// ---------------------------------------------------------------------------
// COMPACT: order-preserving compaction of front rows. 1 block, 512 threads.
// ---------------------------------------------------------------------------
__global__ void __launch_bounds__(512) compact_kernel(const int* __restrict__ pose)
{
    __shared__ int warp_cnt[16];
    int tid = threadIdx.x;
    int lane = tid & 31, wid = tid >> 5;
    int f = (pose[tid] == 1) ? 1 : 0;
    unsigned bal = __ballot_sync(0xffffffffu, f);
    int wpre = __popc(bal & ((1u << lane) - 1u));
    if (lane == 31) warp_cnt[wid] = __popc(bal);
    __syncthreads();
    if (tid < 16) {
        int v = warp_cnt[tid];
        #pragma unroll
        for (int d = 1; d < 16; d <<= 1) {
            int t = __shfl_up_sync(0x0000ffffu, v, d);
            if (tid >= d) v += t;
        }
        warp_cnt[tid] = v;             // inclusive scan
    }
    __syncthreads();
    int base = (wid == 0) ? 0 : warp_cnt[wid - 1];
    if (f) g_idx[base + wpre] = tid;
    if (tid == 511) g_nf = warp_cnt[15];
}

// ---------------------------------------------------------------------------
// GEMM1c split-K on COMPACTED rows: hp[s][ci] = pooled[idx[ci]] @ W1^T chunk
// ---------------------------------------------------------------------------
__global__ void __launch_bounds__(256) gemm1(
    const float* __restrict__ A, const float* __restrict__ Bw,
    float* __restrict__ hp)
{
    __shared__ float As[16][68];
    __shared__ float Bs[16][68];
    int nf = g_nf;
    int m0 = blockIdx.x * 64;
    if (m0 >= nf) return;
    int s  = blockIdx.z;
    int n0 = blockIdx.y * 64;
    int k0 = s * (Cc / S1);
    int tid = threadIdx.x;
    int tx = tid & 15, ty = tid >> 4;
    int r  = tid >> 2;
    int q  = (tid & 3) * 4;
    float acc[4][4] = {};

    int ci   = m0 + r;
    int orig = g_idx[ci < nf ? ci : nf - 1];
    const float* ap = &A [(size_t)orig * Cc + k0 + q];
    const float* bp = &Bw[(size_t)(n0 + r) * Cc + k0 + q];
    float4 areg = *(const float4*)ap;
    float4 breg = *(const float4*)bp;

    #pragma unroll
    for (int kt = 0; kt < Cc / S1; kt += 16) {
        As[q+0][r] = areg.x; As[q+1][r] = areg.y; As[q+2][r] = areg.z; As[q+3][r] = areg.w;
        Bs[q+0][r] = breg.x; Bs[q+1][r] = breg.y; Bs[q+2][r] = breg.z; Bs[q+3][r] = breg.w;
        __syncthreads();
        if (kt + 16 < Cc / S1) {
            areg = *(const float4*)(ap + kt + 16);
            breg = *(const float4*)(bp + kt + 16);
        }
        #pragma unroll
        for (int kk = 0; kk < 16; kk++) {
            float4 a4 = *(const float4*)&As[kk][ty * 4];
            float4 b4 = *(const float4*)&Bs[kk][tx * 4];
            float a[4]  = {a4.x, a4.y, a4.z, a4.w};
            float bb[4] = {b4.x, b4.y, b4.z, b4.w};
            #pragma unroll
            for (int i = 0; i < 4; i++)
                #pragma unroll
                for (int j = 0; j < 4; j++)
                    acc[i][j] = fmaf(a[i], bb[j], acc[i][j]);
        }
        __syncthreads();
    }
    #pragma unroll
    for (int i = 0; i < 4; i++) {
        int m = m0 + ty * 4 + i;
        #pragma unroll
        for (int j = 0; j < 4; j++) {
            int n = n0 + tx * 4 + j;
            hp[((size_t)s * Bb + m) * HIDn + n] = acc[i][j];
        }
    }
}

// ---------------------------------------------------------------------------
// hreduce: h = relu(sum_s hp[s] + b1)  (rows >= nf are finite garbage, unused)
// ---------------------------------------------------------------------------
__global__ void __launch_bounds__(256) hreduce(const float* __restrict__ b1v)
{
    int i4 = blockIdx.x * 256 + threadIdx.x;
    float4 v = *(const float4*)&g_hp[(size_t)i4 * 4];
    #pragma unroll
    for (int s = 1; s < S1; s++) {
        float4 t = *(const float4*)&g_hp[(size_t)s * (Bb * HIDn) + (size_t)i4 * 4];
        v.x += t.x; v.y += t.y; v.z += t.z; v.w += t.w;
    }
    float4 bv = *(const float4*)&b1v[(i4 & 31) * 4];
    v.x = fmaxf(v.x + bv.x, 0.f);
    v.y = fmaxf(v.y + bv.y, 0.f);
    v.z = fmaxf(v.z + bv.z, 0.f);
    v.w = fmaxf(v.w + bv.w, 0.f);
    *(float4*)&g_h[(size_t)i4 * 4] = v;
}

// ---------------------------------------------------------------------------
// ZB GEMM: zbp[s][j][b] = (bmean[:, chunk] @ Wl[:, chunk]^T) partials.
// Grid (8 mtiles, 16 ksplits), 256 threads. Tile: 64 rows x 64 attrs(padded).
// ---------------------------------------------------------------------------
__global__ void __launch_bounds__(256) zb_gemm(const float* __restrict__ Wl)
{
    __shared__ float As [64][68];   // row-major: As[m][kk]
    __shared__ float WlT[64][68];   // WlT[kk][attr], attr>=51 zero
    int m0 = blockIdx.x * 64;
    int s  = blockIdx.y;
    int k0 = s * (Cc / S3);         // 128-wide chunk
    int tid = threadIdx.x;
    int tx = tid & 15, ty = tid >> 4;
    float acc[4][4] = {};

    #pragma unroll
    for (int half = 0; half < 2; half++) {
        int kb = k0 + half * 64;
        {   // A: 64 rows x 64 k, 16 floats per thread
            int r = tid >> 2;
            int q = (tid & 3) * 16;
            const float4* src = (const float4*)&g_bmean[(size_t)(m0 + r) * Cc + kb + q];
            float4 v0 = src[0], v1 = src[1], v2 = src[2], v3 = src[3];
            *(float4*)&As[r][q + 0]  = v0;
            *(float4*)&As[r][q + 4]  = v1;
            *(float4*)&As[r][q + 8]  = v2;
            *(float4*)&As[r][q + 12] = v3;
        }
        for (int idx = tid; idx < 64 * 68; idx += 256) {
            int kk = idx / 68, j = idx - kk * 68;
            WlT[kk][j] = (j < NAT) ? Wl[(size_t)j * Cc + kb + kk] : 0.f;
        }
        __syncthreads();
        #pragma unroll 8
        for (int kk = 0; kk < 64; kk++) {
            float4 w4 = *(const float4*)&WlT[kk][tx * 4];
            float ww[4] = {w4.x, w4.y, w4.z, w4.w};
            #pragma unroll
            for (int i = 0; i < 4; i++) {
                float a = As[ty * 4 + i][kk];
                #pragma unroll
                for (int j = 0; j < 4; j++)
                    acc[i][j] = fmaf(a, ww[j], acc[i][j]);
            }
        }
        __syncthreads();
    }
    #pragma unroll
    for (int j = 0; j < 4; j++) {
        int attr = tx * 4 + j;
        if (attr < NAT) {
            #pragma unroll
            for (int i = 0; i < 4; i++) {
                int b = m0 + ty * 4 + i;
                g_zbp[((size_t)s * NAT + attr) * Bb + b] = acc[i][j];
            }
        }
    }
}

// ---------------------------------------------------------------------------
// GATE (compacted): R5-proven 32x64 tile / 128 threads skeleton.
// Rows are COMPACTED front rows. Epilogue emits pure sigmoid partials
// (no bmean) scattered to original b; guarded writes for ci >= nf.
// ---------------------------------------------------------------------------
__global__ void __launch_bounds__(128) gemm_gate(
    const float* __restrict__ W2,  const float* __restrict__ b2v,
    const float* __restrict__ Wl)
{
    __shared__ __align__(16) float smemBuf[64 * 36 + 64 * 68];   // 26624 B
    float (*As)[36]   = (float(*)[36]) smemBuf;                  // [16][36]
    float (*Bs)[68]   = (float(*)[68])(smemBuf + 16 * 36);       // [16][68]
    float (*gapT)[36] = (float(*)[36]) smemBuf;                  // [64][36]
    float (*WlT)[68]  = (float(*)[68])(smemBuf + 64 * 36);       // [64][68]

    int nf = g_nf;
    int m0 = blockIdx.x * 32;
    if (m0 >= nf) return;
    int n0 = blockIdx.y * 64;
    int tid = threadIdx.x;
    int tx = tid & 15, ty = tid >> 4;       // ty 0..7
    int ra = tid >> 2;
    int qa = (tid & 3) * 4;
    int rb = tid >> 1;
    int qb = (tid & 1) * 8;
    float acc[4][4] = {};

    const float* ap = &g_h[(size_t)(m0 + ra) * HIDn + qa];
    const float* bp = &W2 [(size_t)(n0 + rb) * HIDn + qb];
    float4 areg  = *(const float4*)ap;
    float4 breg0 = *(const float4*)bp;
    float4 breg1 = *(const float4*)(bp + 4);

    #pragma unroll
    for (int kt = 0; kt < HIDn; kt += 16) {
        As[qa+0][ra] = areg.x; As[qa+1][ra] = areg.y; As[qa+2][ra] = areg.z; As[qa+3][ra] = areg.w;
        Bs[qb+0][rb] = breg0.x; Bs[qb+1][rb] = breg0.y; Bs[qb+2][rb] = breg0.z; Bs[qb+3][rb] = breg0.w;
        Bs[qb+4][rb] = breg1.x; Bs[qb+5][rb] = breg1.y; Bs[qb+6][rb] = breg1.z; Bs[qb+7][rb] = breg1.w;
        __syncthreads();
        if (kt + 16 < HIDn) {
            areg  = *(const float4*)(ap + kt + 16);
            breg0 = *(const float4*)(bp + kt + 16);
            breg1 = *(const float4*)(bp + kt + 20);
        }
        #pragma unroll
        for (int kk = 0; kk < 16; kk++) {
            float4 a4 = *(const float4*)&As[kk][ty * 4];
            float4 b4 = *(const float4*)&Bs[kk][tx * 4];
            float a[4]  = {a4.x, a4.y, a4.z, a4.w};
            float bb[4] = {b4.x, b4.y, b4.z, b4.w};
            #pragma unroll
            for (int i = 0; i < 4; i++)
                #pragma unroll
                for (int j = 0; j < 4; j++)
                    acc[i][j] = fmaf(a[i], bb[j], acc[i][j]);
        }
        __syncthreads();
    }

    // epilogue: sig -> gapT (chan-major); rows >= nf produce finite garbage
    // but their zp writes are guarded off below.
    #pragma unroll
    for (int i = 0; i < 4; i++) {
        #pragma unroll
        for (int j = 0; j < 4; j++) {
            int n = n0 + tx * 4 + j;
            float v = acc[i][j] + b2v[n];
            gapT[tx * 4 + j][ty * 4 + i] = 1.0f / (1.0f + expf(-v));
        }
    }
    for (int idx = tid; idx < 64 * 68; idx += 128) {
        int cc = idx / 68, j = idx - cc * 68;
        WlT[cc][j] = (j < NAT) ? Wl[(size_t)j * Cc + n0 + cc] : 0.f;
    }
    __syncthreads();

    float acc2[4][4] = {};
    #pragma unroll 8
    for (int cc = 0; cc < 64; cc++) {
        float4 g4 = *(const float4*)&gapT[cc][ty * 4];
        float4 w4 = *(const float4*)&WlT [cc][tx * 4];
        float gg[4] = {g4.x, g4.y, g4.z, g4.w};
        float ww[4] = {w4.x, w4.y, w4.z, w4.w};
        #pragma unroll
        for (int i = 0; i < 4; i++)
            #pragma unroll
            for (int j = 0; j < 4; j++)
                acc2[i][j] = fmaf(gg[i], ww[j], acc2[i][j]);
    }
    int nt = blockIdx.y;
    int ob[4]; bool val[4];
    #pragma unroll
    for (int i = 0; i < 4; i++) {
        int ci = m0 + ty * 4 + i;
        val[i] = (ci < nf);
        ob[i]  = val[i] ? g_idx[ci] : 0;
    }
    #pragma unroll
    for (int j = 0; j < 4; j++) {
        int attr = tx * 4 + j;
        if (attr < NAT) {
            #pragma unroll
            for (int i = 0; i < 4; i++) {
                if (val[i])
                    g_zp[((size_t)nt * NAT + attr) * Bb + ob[i]] = acc2[i][j];
            }
        }
    }
}

// ---------------------------------------------------------------------------
// BN: z = bias + sum_s zbp + front * sum_nt zp, then batch-norm.
// ---------------------------------------------------------------------------
__global__ void __launch_bounds__(256) bn_kernel(
    const float* __restrict__ blv, const float* __restrict__ gam,
    const float* __restrict__ bet, const int* __restrict__ pose,
    float* __restrict__ out)
{
    __shared__ float zbuf[Bb];
    __shared__ float red[256];
    int j   = blockIdx.x;
    int tid = threadIdx.x;
    float bias = blv[j];
    float lsum = 0.f;
    for (int b = tid; b < Bb; b += 256) {
        float z = bias;
        #pragma unroll
        for (int s = 0; s < S3; s++)
            z += g_zbp[((size_t)s * NAT + j) * Bb + b];
        float z2 = 0.f;
        #pragma unroll
        for (int nt = 0; nt < NTIL; nt++)
            z2 += g_zp[((size_t)nt * NAT + j) * Bb + b];
        z += (pose[b] == 1) ? z2 : 0.f;
        zbuf[b] = z;
        lsum += z;
    }
    red[tid] = lsum;
    __syncthreads();
    for (int off = 128; off; off >>= 1) {
        if (tid < off) red[tid] += red[tid + off];
        __syncthreads();
    }
    float mu = red[0] * (1.0f / Bb);
    __syncthreads();
    float lvar = 0.f;
    for (int b = tid; b < Bb; b += 256) {
        float d = zbuf[b] - mu;
        lvar += d * d;
    }
    red[tid] = lvar;
    __syncthreads();
    for (int off = 128; off; off >>= 1) {
        if (tid < off) red[tid] += red[tid + off];
        __syncthreads();
    }
    float inv = rsqrtf(red[0] * (1.0f / Bb) + 1e-5f);
    float ga = gam[j], be = bet[j];
    for (int b = tid; b < Bb; b += 256)
        out[(size_t)b * NAT + j] = ga * (zbuf[b] - mu) * inv + be;
}

// ---------------------------------------------------------------------------
extern "C" void kernel_launch(void* const* d_in, const int* in_sizes, int n_in,
                              void* d_out, int out_size)
{
    const float* body = (const float*)d_in[0];
    const float* face = (const float*)d_in[1];
    const int*   pose = (const int*)  d_in[2];
    const float* Af   = (const float*)d_in[3];
    const float* W1   = (const float*)d_in[4];
    const float* b1v  = (const float*)d_in[5];
    const float* W2   = (const float*)d_in[6];
    const float* b2v  = (const float*)d_in[7];
    const float* Wl   = (const float*)d_in[8];
    const float* blv  = (const float*)d_in[9];
    const float* gam  = (const float*)d_in[10];
    const float* bet  = (const float*)d_in[11];
    float* out = (float*)d_out;

    float *pooled_p, *hp_p;
    cudaGetSymbolAddress((void**)&pooled_p, g_pooled);
    cudaGetSymbolAddress((void**)&hp_p,     g_hp);

    // 1) streaming reduce: pooled max + body mean
    k1_reduce<<<(Bb * Cc) / 64, 256>>>(body, face, Af, pose);
    // 2) compact front rows
    compact_kernel<<<1, 512>>>(pose);
    // 3) hp[s] = pooledC @ W1^T  (compacted rows)
    gemm1<<<dim3(Bb / 64, HIDn / 64, S1), 256>>>(pooled_p, W1, hp_p);
    // 4) h = relu(sum hp + b1)
    hreduce<<<(Bb * HIDn / 4) / 256, 256>>>(b1v);
    // 5) zbp = bmean @ Wl^T  (split-K partials, all rows)
    zb_gemm<<<dim3(Bb / 64, S3), 256>>>(Wl);
    // 6) gate GEMM on compacted rows + fused sig@Wl partials
    gemm_gate<<<dim3(Bb / 32, NTIL), 128>>>(W2, b2v, Wl);
    // 7) combine partials + bias + batchnorm
    bn_kernel<<<NAT, 256>>>(blv, gam, bet, pose, out);
}

// round 10
// speedup vs baseline: 1.2346x; 1.2346x over previous
#include <cuda_runtime.h>
#include <math.h>
#include <float.h>

#define Bb   512
#define Cc   2048
#define HWn  48
#define NAT  51
#define HIDn 128
#define S1   16    // K-splits for pooled @ W1^T  (K=2048 -> 128/split)
#define NTIL 32    // channel tiles in gate kernel (2048/64)

// Scratch (static __device__ globals: allocation-free rule)
__device__ float g_pooled[Bb * Cc];            // max_hw(body*A*face), 0 for non-front rows
__device__ float g_bmean [Bb * Cc];            // mean_hw(body)
__device__ float g_hp    [S1 * Bb * HIDn];     // split-K partials of pooled @ W1^T
__device__ float g_h     [Bb * HIDn];          // relu(sum hp + b1)
__device__ float g_zp    [NTIL * NAT * Bb];    // per-n-tile partials of gap @ Wl^T, [nt][j][b]

// ---------------------------------------------------------------------------
// K1: streaming pass, float4 loads (R5 version — proven, near HBM bound).
// ---------------------------------------------------------------------------
__global__ void __launch_bounds__(256) k1_reduce(
    const float* __restrict__ body, const float* __restrict__ face,
    const float* __restrict__ Af,   const int*   __restrict__ pose)
{
    __shared__ float sm_s[8][96];
    __shared__ float sm_m[8][96];
    __shared__ float out_s[64], out_m[64];
    int tid  = threadIdx.x;
    int wid  = tid >> 5;
    int lane = tid & 31;
    int blk_ch = blockIdx.x * 64;
    int b = blk_ch >> 11;
    bool front = (pose[b] == 1);
    int wbase = blk_ch + wid * 8;

    const float4* bp4 = (const float4*)body + (size_t)wbase * 12;
    float4 bv[3];
    #pragma unroll
    for (int k = 0; k < 3; k++)
        bv[k] = bp4[k * 32 + lane];
    if (front) {
        const float4* fp4 = (const float4*)face + (size_t)wbase * 12;
        const float4* ap4 = (const float4*)Af   + (size_t)(wbase & (Cc - 1)) * 12;
        #pragma unroll
        for (int k = 0; k < 3; k++) {
            float4 fv = fp4[k * 32 + lane];
            float4 av = ap4[k * 32 + lane];
            float m01 = fmaxf(bv[k].x * av.x * fv.x, bv[k].y * av.y * fv.y);
            float m23 = fmaxf(bv[k].z * av.z * fv.z, bv[k].w * av.w * fv.w);
            sm_m[wid][k * 32 + lane] = fmaxf(m01, m23);
        }
    }
    #pragma unroll
    for (int k = 0; k < 3; k++)
        sm_s[wid][k * 32 + lane] = (bv[k].x + bv[k].y) + (bv[k].z + bv[k].w);
    __syncthreads();

    {
        int chl = tid >> 2;
        int w2  = chl >> 3;
        int off = (chl & 7) * 12 + (tid & 3) * 3;
        float ss = sm_s[w2][off] + sm_s[w2][off + 1] + sm_s[w2][off + 2];
        ss += __shfl_xor_sync(0xffffffffu, ss, 1);
        ss += __shfl_xor_sync(0xffffffffu, ss, 2);
        float mm = 0.f;
        if (front) {
            mm = fmaxf(fmaxf(sm_m[w2][off], sm_m[w2][off + 1]), sm_m[w2][off + 2]);
            mm = fmaxf(mm, __shfl_xor_sync(0xffffffffu, mm, 1));
            mm = fmaxf(mm, __shfl_xor_sync(0xffffffffu, mm, 2));
        }
        if ((tid & 3) == 0) {
            out_s[chl] = ss * (1.0f / 48.0f);
            out_m[chl] = mm;
        }
    }
    __syncthreads();
    if (tid < 64)        g_bmean [blk_ch + tid]      = out_s[tid];
    else if (tid < 128)  g_pooled[blk_ch + tid - 64] = out_m[tid - 64];
}

// ---------------------------------------------------------------------------
// GEMM1 split-K: hp[s] = pooled[512, k-chunk] @ W1[128, k-chunk]^T (unchanged)
// ---------------------------------------------------------------------------
__global__ void __launch_bounds__(256) gemm1(
    const float* __restrict__ A, const float* __restrict__ Bw,
    float* __restrict__ hp)
{
    __shared__ float As[16][68];
    __shared__ float Bs[16][68];
    int s  = blockIdx.z;
    int m0 = blockIdx.x * 64;
    int n0 = blockIdx.y * 64;
    int k0 = s * (Cc / S1);
    int tid = threadIdx.x;
    int tx = tid & 15, ty = tid >> 4;
    int r  = tid >> 2;
    int q  = (tid & 3) * 4;
    float acc[4][4] = {};

    const float* ap = &A [(size_t)(m0 + r) * Cc + k0 + q];
    const float* bp = &Bw[(size_t)(n0 + r) * Cc + k0 + q];
    float4 areg = *(const float4*)ap;
    float4 breg = *(const float4*)bp;

    #pragma unroll
    for (int kt = 0; kt < Cc / S1; kt += 16) {
        As[q+0][r] = areg.x; As[q+1][r] = areg.y; As[q+2][r] = areg.z; As[q+3][r] = areg.w;
        Bs[q+0][r] = breg.x; Bs[q+1][r] = breg.y; Bs[q+2][r] = breg.z; Bs[q+3][r] = breg.w;
        __syncthreads();
        if (kt + 16 < Cc / S1) {
            areg = *(const float4*)(ap + kt + 16);
            breg = *(const float4*)(bp + kt + 16);
        }
        #pragma unroll
        for (int kk = 0; kk < 16; kk++) {
            float4 a4 = *(const float4*)&As[kk][ty * 4];
            float4 b4 = *(const float4*)&Bs[kk][tx * 4];
            float a[4]  = {a4.x, a4.y, a4.z, a4.w};
            float bb[4] = {b4.x, b4.y, b4.z, b4.w};
            #pragma unroll
            for (int i = 0; i < 4; i++)
                #pragma unroll
                for (int j = 0; j < 4; j++)
                    acc[i][j] = fmaf(a[i], bb[j], acc[i][j]);
        }
        __syncthreads();
    }
    #pragma unroll
    for (int i = 0; i < 4; i++) {
        int m = m0 + ty * 4 + i;
        #pragma unroll
        for (int j = 0; j < 4; j++) {
            int n = n0 + tx * 4 + j;
            hp[((size_t)s * Bb + m) * HIDn + n] = acc[i][j];
        }
    }
}

// ---------------------------------------------------------------------------
// hreduce v2: 256 blocks, scalar per thread (fully coalesced, all SMs used).
// h[i] = relu(b1[i & 127] + sum_s hp[s][i]),  i over 512*128 = 65536.
// ---------------------------------------------------------------------------
__global__ void __launch_bounds__(256) hreduce(const float* __restrict__ b1v)
{
    int i = blockIdx.x * 256 + threadIdx.x;           // 65536 threads
    float v = g_hp[i];
    #pragma unroll
    for (int s = 1; s < S1; s++)
        v += g_hp[(size_t)s * (Bb * HIDn) + i];
    v += b1v[i & (HIDn - 1)];
    g_h[i] = fmaxf(v, 0.f);
}

// ---------------------------------------------------------------------------
// GATE (R3 version — fastest measured, 24.6us): 64(batch)x64(chan) tile,
// 256 threads, grid (8, 32). gap = bmean + front*sigmoid(h @ W2^T + b2),
// fused z-partial epilogue. WlT padded to 68 cols (reads at tx*4 <= 63 safe).
// ---------------------------------------------------------------------------
__global__ void __launch_bounds__(256) gemm_gate(
    const float* __restrict__ W2,  const float* __restrict__ b2v,
    const float* __restrict__ Wl,  const int*   __restrict__ pose)
{
    __shared__ __align__(16) float smemBuf[64 * 68 + 64 * 68];   // 34816 B
    float (*As)[68]   = (float(*)[68]) smemBuf;                  // [16][68]
    float (*Bs)[68]   = (float(*)[68])(smemBuf + 16 * 68);       // [16][68]
    float (*gapT)[68] = (float(*)[68]) smemBuf;                  // [64][68]
    float (*WlT)[68]  = (float(*)[68])(smemBuf + 64 * 68);       // [64][68]

    int m0 = blockIdx.x * 64;
    int n0 = blockIdx.y * 64;
    int tid = threadIdx.x;
    int tx = tid & 15, ty = tid >> 4;
    int r  = tid >> 2;
    int q  = (tid & 3) * 4;
    float acc[4][4] = {};

    const float* ap = &g_h[(size_t)(m0 + r) * HIDn + q];
    const float* bp = &W2 [(size_t)(n0 + r) * HIDn + q];
    float4 areg = *(const float4*)ap;
    float4 breg = *(const float4*)bp;

    #pragma unroll
    for (int kt = 0; kt < HIDn; kt += 16) {
        As[q+0][r] = areg.x; As[q+1][r] = areg.y; As[q+2][r] = areg.z; As[q+3][r] = areg.w;
        Bs[q+0][r] = breg.x; Bs[q+1][r] = breg.y; Bs[q+2][r] = breg.z; Bs[q+3][r] = breg.w;
        __syncthreads();
        if (kt + 16 < HIDn) {
            areg = *(const float4*)(ap + kt + 16);
            breg = *(const float4*)(bp + kt + 16);
        }
        #pragma unroll
        for (int kk = 0; kk < 16; kk++) {
            float4 a4 = *(const float4*)&As[kk][ty * 4];
            float4 b4 = *(const float4*)&Bs[kk][tx * 4];
            float a[4]  = {a4.x, a4.y, a4.z, a4.w};
            float bb[4] = {b4.x, b4.y, b4.z, b4.w};
            #pragma unroll
            for (int i = 0; i < 4; i++)
                #pragma unroll
                for (int j = 0; j < 4; j++)
                    acc[i][j] = fmaf(a[i], bb[j], acc[i][j]);
        }
        __syncthreads();
    }

    // --- epilogue: gap values -> gapT (chan-major). As/Bs reuse is safe:
    // mainloop ends with __syncthreads(), gapT/WlT are disjoint regions.
    #pragma unroll
    for (int i = 0; i < 4; i++) {
        int m = m0 + ty * 4 + i;
        float fr = (pose[m] == 1) ? 1.0f : 0.0f;
        #pragma unroll
        for (int j = 0; j < 4; j++) {
            int n = n0 + tx * 4 + j;
            float v = acc[i][j] + b2v[n];
            float g = 1.0f / (1.0f + expf(-v));
            gapT[tx * 4 + j][ty * 4 + i] =
                g_bmean[(size_t)m * Cc + n] + fr * g;
        }
    }
    // Load Wl chunk (51 attrs x 64 channels) transposed into WlT[cc][j];
    // zero-fill the full padded width j=51..67.
    for (int idx = tid; idx < 64 * 68; idx += 256) {
        int cc = idx / 68, j = idx - cc * 68;
        WlT[cc][j] = (j < NAT) ? Wl[(size_t)j * Cc + n0 + cc] : 0.f;
    }
    __syncthreads();

    // mini-GEMM: zpart[row, attr] = sum_cc gapT[cc][row] * WlT[cc][attr]
    float acc2[4][4] = {};
    #pragma unroll 8
    for (int cc = 0; cc < 64; cc++) {
        float4 g4 = *(const float4*)&gapT[cc][ty * 4];
        float4 w4 = *(const float4*)&WlT [cc][tx * 4];
        float gg[4] = {g4.x, g4.y, g4.z, g4.w};
        float ww[4] = {w4.x, w4.y, w4.z, w4.w};
        #pragma unroll
        for (int i = 0; i < 4; i++)
            #pragma unroll
            for (int j = 0; j < 4; j++)
                acc2[i][j] = fmaf(gg[i], ww[j], acc2[i][j]);
    }
    int nt = blockIdx.y;
    #pragma unroll
    for (int j = 0; j < 4; j++) {
        int attr = tx * 4 + j;
        if (attr < NAT) {
            #pragma unroll
            for (int i = 0; i < 4; i++) {
                int m = m0 + ty * 4 + i;
                g_zp[((size_t)nt * NAT + attr) * Bb + m] = acc2[i][j];
            }
        }
    }
}

// ---------------------------------------------------------------------------
// BN: one block per attribute (NTIL=32 partials).
// ---------------------------------------------------------------------------
__global__ void __launch_bounds__(256) bn_kernel(
    const float* __restrict__ blv, const float* __restrict__ gam,
    const float* __restrict__ bet, float* __restrict__ out)
{
    __shared__ float zbuf[Bb];
    __shared__ float red[256];
    int j   = blockIdx.x;
    int tid = threadIdx.x;
    float bias = blv[j];
    float lsum = 0.f;
    for (int b = tid; b < Bb; b += 256) {
        float z = bias;
        #pragma unroll
        for (int nt = 0; nt < NTIL; nt++)
            z += g_zp[((size_t)nt * NAT + j) * Bb + b];
        zbuf[b] = z;
        lsum += z;
    }
    red[tid] = lsum;
    __syncthreads();
    for (int off = 128; off; off >>= 1) {
        if (tid < off) red[tid] += red[tid + off];
        __syncthreads();
    }
    float mu = red[0] * (1.0f / Bb);
    __syncthreads();
    float lvar = 0.f;
    for (int b = tid; b < Bb; b += 256) {
        float d = zbuf[b] - mu;
        lvar += d * d;
    }
    red[tid] = lvar;
    __syncthreads();
    for (int off = 128; off; off >>= 1) {
        if (tid < off) red[tid] += red[tid + off];
        __syncthreads();
    }
    float inv = rsqrtf(red[0] * (1.0f / Bb) + 1e-5f);
    float ga = gam[j], be = bet[j];
    for (int b = tid; b < Bb; b += 256)
        out[(size_t)b * NAT + j] = ga * (zbuf[b] - mu) * inv + be;
}

// ---------------------------------------------------------------------------
extern "C" void kernel_launch(void* const* d_in, const int* in_sizes, int n_in,
                              void* d_out, int out_size)
{
    const float* body = (const float*)d_in[0];
    const float* face = (const float*)d_in[1];
    const int*   pose = (const int*)  d_in[2];
    const float* Af   = (const float*)d_in[3];
    const float* W1   = (const float*)d_in[4];
    const float* b1v  = (const float*)d_in[5];
    const float* W2   = (const float*)d_in[6];
    const float* b2v  = (const float*)d_in[7];
    const float* Wl   = (const float*)d_in[8];
    const float* blv  = (const float*)d_in[9];
    const float* gam  = (const float*)d_in[10];
    const float* bet  = (const float*)d_in[11];
    float* out = (float*)d_out;

    float *pooled_p, *hp_p;
    cudaGetSymbolAddress((void**)&pooled_p, g_pooled);
    cudaGetSymbolAddress((void**)&hp_p,     g_hp);

    // 1) streaming reduce: pooled max + body mean
    k1_reduce<<<(Bb * Cc) / 64, 256>>>(body, face, Af, pose);
    // 2) hp[s] = pooled @ W1^T  (16-way split-K partials)
    gemm1<<<dim3(Bb / 64, HIDn / 64, S1), 256>>>(pooled_p, W1, hp_p);
    // 3) h = relu(sum hp + b1)  (256 blocks, coalesced scalar)
    hreduce<<<(Bb * HIDn) / 256, 256>>>(b1v);
    // 4) gate GEMM (R3 config: 64x64, 256 thr) + fused z-partial epilogue
    gemm_gate<<<dim3(Bb / 64, NTIL), 256>>>(W2, b2v, Wl, pose);
    // 5) reduce partials + bias + batchnorm
    bn_kernel<<<NAT, 256>>>(blv, gam, bet, out);
}